// round 5
// baseline (speedup 1.0000x reference)
#include <cuda_runtime.h>

// GravityDecoder: per-edge fused gather + linear + log-dist + sigmoid.
// Inputs (metadata order):
//   d_in[0]: z          float32 [N, 128]
//   d_in[1]: edge_index int32   [2, E]
//   d_in[2]: W          float32 [128]
//   d_in[3]: b          float32 scalar
// Output: float32 [4, E] = (logits, prob, m_j, dist2) concatenated.
//
// Layout: 16 lanes per edge (2 edges per warp) -> 16 payload regs, 8 W regs,
// ~38 regs total so 6 blocks/SM (75% occupancy). Index loads software-
// pipelined; streaming cache hints keep z resident in L2.

#define WARPS_PER_BLOCK 8
#define THREADS (WARPS_PER_BLOCK * 32)

__global__ __launch_bounds__(THREADS, 6) void gravity_decoder_kernel(
    const float* __restrict__ z,
    const int* __restrict__ edge_index,
    const float* __restrict__ W,
    const float* __restrict__ b_ptr,
    float* __restrict__ out,
    int E)
{
    const int lane   = threadIdx.x & 31;
    const int sub    = lane & 15;       // sublane within 16-lane group
    const int group  = lane >> 4;       // 0..1 : which edge of the 2
    const int warp   = (int)((blockIdx.x * (unsigned)blockDim.x + threadIdx.x) >> 5);
    const int nwarps = (int)((gridDim.x * (unsigned)blockDim.x) >> 5);
    const int stride = nwarps * 2;

    const float b = *b_ptr;

    const float4* __restrict__ Wf4 = reinterpret_cast<const float4*>(W);
    const float4 w0 = Wf4[sub];
    const float4 w1 = Wf4[sub + 16];

    float* __restrict__ out_logits = out;
    float* __restrict__ out_prob   = out + (size_t)E;
    float* __restrict__ out_mj     = out + 2 * (size_t)E;
    float* __restrict__ out_d2     = out + 3 * (size_t)E;

    int e2 = warp * 2;
    if (e2 >= E) return;

    // Prologue: indices for first iteration
    {
        const int e  = e2 + group;
        const int es = (e < E) ? e : (E - 1);
        // fallthrough into loop with src/dst loaded below
    }
    int e  = e2 + group;
    int es = (e < E) ? e : (E - 1);
    int src = __ldcs(edge_index + es);
    int dst = __ldcs(edge_index + es + (size_t)E);

    for (; e2 < E; e2 += stride) {
        const int  ecur  = e2 + group;
        const bool alive = (ecur < E);

        const float4* __restrict__ zi4 = reinterpret_cast<const float4*>(z + (size_t)src * 128);
        const float4* __restrict__ zj4 = reinterpret_cast<const float4*>(z + (size_t)dst * 128);

        // Issue all 4 gathers up front (MLP)
        const float4 a0 = zi4[sub];
        const float4 a1 = zi4[sub + 16];
        const float4 c0 = zj4[sub];
        const float4 c1 = zj4[sub + 16];

        // Prefetch next iteration's indices while gathers are in flight
        const int e2n = e2 + stride;
        if (e2n < E) {
            const int en  = e2n + group;
            const int esn = (en < E) ? en : (E - 1);
            src = __ldcs(edge_index + esn);
            dst = __ldcs(edge_index + esn + (size_t)E);
        }

        float mj = c0.x * w0.x + c0.y * w0.y + c0.z * w0.z + c0.w * w0.w;
        mj      += c1.x * w1.x + c1.y * w1.y + c1.z * w1.z + c1.w * w1.w;

        float d2;
        {
            float dx, dy, dz, dw;
            dx = a0.x - c0.x; dy = a0.y - c0.y; dz = a0.z - c0.z; dw = a0.w - c0.w;
            d2  = dx * dx + dy * dy + dz * dz + dw * dw;
            dx = a1.x - c1.x; dy = a1.y - c1.y; dz = a1.z - c1.z; dw = a1.w - c1.w;
            d2 += dx * dx + dy * dy + dz * dz + dw * dw;
        }

        // 4-step butterfly within each 16-lane group
        #pragma unroll
        for (int off = 8; off > 0; off >>= 1) {
            mj += __shfl_xor_sync(0xffffffffu, mj, off);
            d2 += __shfl_xor_sync(0xffffffffu, d2, off);
        }

        mj += b;
        d2 += 1e-7f;
        const float logit = mj - __logf(d2);

        if (alive) {
            if (sub == 0)      __stcs(out_logits + ecur, logit);
            else if (sub == 1) __stcs(out_prob + ecur, __fdividef(1.0f, 1.0f + __expf(-logit)));
            else if (sub == 2) __stcs(out_mj + ecur, mj);
            else if (sub == 3) __stcs(out_d2 + ecur, d2);
        }
    }
}

extern "C" void kernel_launch(void* const* d_in, const int* in_sizes, int n_in,
                              void* d_out, int out_size)
{
    const float* z   = (const float*)d_in[0];
    const int*   ei  = (const int*)d_in[1];
    const float* W   = (const float*)d_in[2];
    const float* b   = (const float*)d_in[3];
    float*       out = (float*)d_out;

    const int E = in_sizes[1] / 2;

    int blocks = (E + WARPS_PER_BLOCK * 2 - 1) / (WARPS_PER_BLOCK * 2);
    if (blocks > 4736) blocks = 4736;

    gravity_decoder_kernel<<<blocks, THREADS>>>(z, ei, W, b, out, E);
}

// round 6
// speedup vs baseline: 1.4111x; 1.4111x over previous
#include <cuda_runtime.h>

// GravityDecoder: per-edge fused gather + linear + log-dist + sigmoid.
// Inputs (metadata order):
//   d_in[0]: z          float32 [N, 128]
//   d_in[1]: edge_index int32   [2, E]
//   d_in[2]: W          float32 [128]
//   d_in[3]: b          float32 scalar
// Output: float32 [4, E] = (logits, prob, m_j, dist2) concatenated.
//
// Layout (back to R4's winner): 8 lanes per edge, 4 edges per warp,
// 8 float4 gathers in flight per thread. W lives in shared memory so the
// register count fits 6 blocks/SM (48 warps) -> 384 outstanding gathers/SM.

#define WARPS_PER_BLOCK 8
#define THREADS (WARPS_PER_BLOCK * 32)

__global__ __launch_bounds__(THREADS, 6) void gravity_decoder_kernel(
    const float* __restrict__ z,
    const int* __restrict__ edge_index,
    const float* __restrict__ W,
    const float* __restrict__ b_ptr,
    float* __restrict__ out,
    int E)
{
    __shared__ float s_w[128];
    if (threadIdx.x < 128) s_w[threadIdx.x] = W[threadIdx.x];
    __syncthreads();

    const int lane   = threadIdx.x & 31;
    const int sub    = lane & 7;        // sublane within 8-lane group
    const int group  = lane >> 3;       // 0..3 : which edge of the 4
    const int warp   = (int)((blockIdx.x * (unsigned)blockDim.x + threadIdx.x) >> 5);
    const int nwarps = (int)((gridDim.x * (unsigned)blockDim.x) >> 5);
    const int stride = nwarps * 4;

    const float b = *b_ptr;
    const float4* __restrict__ sw4 = reinterpret_cast<const float4*>(s_w);

    float* __restrict__ out_logits = out;
    float* __restrict__ out_prob   = out + (size_t)E;
    float* __restrict__ out_mj     = out + 2 * (size_t)E;
    float* __restrict__ out_d2     = out + 3 * (size_t)E;

    int e4 = warp * 4;
    if (e4 >= E) return;

    // Prologue: indices for the first iteration
    int e  = e4 + group;
    int es = (e < E) ? e : (E - 1);
    int src = __ldcs(edge_index + es);
    int dst = __ldcs(edge_index + es + (size_t)E);

    for (; e4 < E; e4 += stride) {
        const int  ecur  = e4 + group;
        const bool alive = (ecur < E);

        const float4* __restrict__ zi4 = reinterpret_cast<const float4*>(z + (size_t)src * 128);
        const float4* __restrict__ zj4 = reinterpret_cast<const float4*>(z + (size_t)dst * 128);

        // Issue all 8 gathers up front (MLP)
        const float4 a0 = zi4[sub];
        const float4 a1 = zi4[sub + 8];
        const float4 a2 = zi4[sub + 16];
        const float4 a3 = zi4[sub + 24];
        const float4 c0 = zj4[sub];
        const float4 c1 = zj4[sub + 8];
        const float4 c2 = zj4[sub + 16];
        const float4 c3 = zj4[sub + 24];

        // Prefetch next iteration's indices while gathers are in flight
        const int e4n = e4 + stride;
        if (e4n < E) {
            const int en  = e4n + group;
            const int esn = (en < E) ? en : (E - 1);
            src = __ldcs(edge_index + esn);
            dst = __ldcs(edge_index + esn + (size_t)E);
        }

        // W from shared (rematerializable -> low register pressure)
        const float4 w0 = sw4[sub];
        const float4 w1 = sw4[sub + 8];
        const float4 w2 = sw4[sub + 16];
        const float4 w3 = sw4[sub + 24];

        float mj = c0.x * w0.x + c0.y * w0.y + c0.z * w0.z + c0.w * w0.w;
        mj      += c1.x * w1.x + c1.y * w1.y + c1.z * w1.z + c1.w * w1.w;
        mj      += c2.x * w2.x + c2.y * w2.y + c2.z * w2.z + c2.w * w2.w;
        mj      += c3.x * w3.x + c3.y * w3.y + c3.z * w3.z + c3.w * w3.w;

        float d2;
        {
            float dx, dy, dz, dw;
            dx = a0.x - c0.x; dy = a0.y - c0.y; dz = a0.z - c0.z; dw = a0.w - c0.w;
            d2  = dx * dx + dy * dy + dz * dz + dw * dw;
            dx = a1.x - c1.x; dy = a1.y - c1.y; dz = a1.z - c1.z; dw = a1.w - c1.w;
            d2 += dx * dx + dy * dy + dz * dz + dw * dw;
            dx = a2.x - c2.x; dy = a2.y - c2.y; dz = a2.z - c2.z; dw = a2.w - c2.w;
            d2 += dx * dx + dy * dy + dz * dz + dw * dw;
            dx = a3.x - c3.x; dy = a3.y - c3.y; dz = a3.z - c3.z; dw = a3.w - c3.w;
            d2 += dx * dx + dy * dy + dz * dz + dw * dw;
        }

        // 3-step butterfly within each 8-lane group
        #pragma unroll
        for (int off = 4; off > 0; off >>= 1) {
            mj += __shfl_xor_sync(0xffffffffu, mj, off);
            d2 += __shfl_xor_sync(0xffffffffu, d2, off);
        }

        mj += b;
        d2 += 1e-7f;
        const float logit = mj - __logf(d2);

        if (alive) {
            if (sub == 0)      __stcs(out_logits + ecur, logit);
            else if (sub == 1) __stcs(out_prob + ecur, __fdividef(1.0f, 1.0f + __expf(-logit)));
            else if (sub == 2) __stcs(out_mj + ecur, mj);
            else if (sub == 3) __stcs(out_d2 + ecur, d2);
        }
    }
}

extern "C" void kernel_launch(void* const* d_in, const int* in_sizes, int n_in,
                              void* d_out, int out_size)
{
    const float* z   = (const float*)d_in[0];
    const int*   ei  = (const int*)d_in[1];
    const float* W   = (const float*)d_in[2];
    const float* b   = (const float*)d_in[3];
    float*       out = (float*)d_out;

    const int E = in_sizes[1] / 2;

    int blocks = (E + WARPS_PER_BLOCK * 4 - 1) / (WARPS_PER_BLOCK * 4);
    if (blocks > 4736) blocks = 4736;

    gravity_decoder_kernel<<<blocks, THREADS>>>(z, ei, W, b, out, E);
}